// round 3
// baseline (speedup 1.0000x reference)
#include <cuda_runtime.h>
#include <cstdint>
#include <cstddef>

#define NN     50000
#define HID    64
#define EMAX   800000
#define IN_DIM 512

// ---------------------------------------------------------------------------
// Scratch (__device__ globals; no allocation allowed)
// ---------------------------------------------------------------------------
__device__ __align__(256) float g_dinv[NN];
__device__ int   g_cnt[NN];
__device__ int   g_rowptr[NN + 1];
__device__ int   g_cursor[NN];
__device__ int   g_col[EMAX];
__device__ __align__(256) float g_bufA[NN * HID];
__device__ __align__(256) float g_bufB[NN * HID];

// ---------------------------------------------------------------------------
// CSR build: count -> scan(+dinv) -> fill
// ---------------------------------------------------------------------------
__global__ void k_zero_cnt(int* cnt, int n) {
    int i = blockIdx.x * blockDim.x + threadIdx.x;
    if (i < n) cnt[i] = 0;
}

__global__ void k_count(const int* __restrict__ dst, int* cnt, int E) {
    int e = blockIdx.x * blockDim.x + threadIdx.x;
    if (e < E) atomicAdd(&cnt[dst[e]], 1);
}

// single block, 1024 threads: exclusive scan of cnt -> rowptr/cursor, dinv = rsqrt(cnt+1)
__global__ void __launch_bounds__(1024)
k_scan(const int* __restrict__ cnt, int* rowptr, int* cursor,
       float* dinv, int n) {
    const int T = 1024;
    const int t = threadIdx.x;
    const int chunk = (n + T - 1) / T;
    const int beg = t * chunk;
    const int end = min(beg + chunk, n);

    int s = 0;
    for (int i = beg; i < end; i++) s += cnt[i];

    // block exclusive scan of per-thread sums
    __shared__ int wsum[32];
    int lane = t & 31, wid = t >> 5;
    int v = s;
#pragma unroll
    for (int d = 1; d < 32; d <<= 1) {
        int u = __shfl_up_sync(0xffffffffu, v, d);
        if (lane >= d) v += u;
    }
    if (lane == 31) wsum[wid] = v;
    __syncthreads();
    if (wid == 0) {
        int w = wsum[lane];
#pragma unroll
        for (int d = 1; d < 32; d <<= 1) {
            int u = __shfl_up_sync(0xffffffffu, w, d);
            if (lane >= d) w += u;
        }
        wsum[lane] = w;
    }
    __syncthreads();
    int excl = v - s + (wid > 0 ? wsum[wid - 1] : 0);

    int run = excl;
    for (int i = beg; i < end; i++) {
        rowptr[i] = run;
        cursor[i] = run;
        dinv[i]   = rsqrtf((float)(cnt[i] + 1));
        run += cnt[i];
    }
    if (end == n && beg < n) rowptr[n] = run;
}

__global__ void k_fill(const int* __restrict__ src, const int* __restrict__ dst,
                       int* cursor, int* col, int E) {
    int e = blockIdx.x * blockDim.x + threadIdx.x;
    if (e >= E) return;
    int d = dst[e];
    int pos = atomicAdd(&cursor[d], 1);
    col[pos] = src[e];
}

// ---------------------------------------------------------------------------
// tf32 tensor-core GEMM, cp.async 2-stage pipeline, BK=32.
//   hn[row] = (X @ W)[row] * dinv[row]
// BM=128, BN=64(full). 256 threads = 8 warps (4M x 2N), warp tile 32x32.
// ---------------------------------------------------------------------------
#define BM 128
#define BK 32
#define PA 36   // A row stride (floats): 144B, 16B-aligned, conflict-free frags
#define PB 72   // B row stride (floats): 288B, 16B-aligned, conflict-free frags

#define GEMM_SMEM_BYTES ((2 * BM * PA + 2 * BK * PB) * 4)

__device__ __forceinline__ uint32_t cvt_tf32(float x) {
    uint32_t r;
    asm("cvt.rna.tf32.f32 %0, %1;" : "=r"(r) : "f"(x));
    return r;
}

template <int K>
__global__ void __launch_bounds__(256)
k_gemm(const float* __restrict__ X, const float* __restrict__ W,
       const float* __restrict__ dinv, float* __restrict__ hn, int M) {
    extern __shared__ float smem[];
    float* as = smem;                 // [2][BM*PA]
    float* ws = smem + 2 * BM * PA;   // [2][BK*PB]

    const int t    = threadIdx.x;
    const int m0   = blockIdx.x * BM;
    const int lane = t & 31;
    const int wid  = t >> 5;
    const int wm   = wid >> 1;
    const int wn   = wid & 1;
    const int g    = lane >> 2;
    const int tig  = lane & 3;

    float c[2][4][4];
#pragma unroll
    for (int mt = 0; mt < 2; mt++)
#pragma unroll
        for (int nt = 0; nt < 4; nt++)
#pragma unroll
            for (int i = 0; i < 4; i++) c[mt][nt][i] = 0.0f;

    // --- async stage loader: A 128x32 (1024 x 16B), B 32x64 (512 x 16B)
    auto load_stage = [&](int buf, int k0) {
        float* asb = as + buf * BM * PA;
        float* wsb = ws + buf * BK * PB;
#pragma unroll
        for (int i = 0; i < 4; i++) {
            int G = i * 256 + t;
            int row = G >> 3, gg = G & 7;
            bool ok = (m0 + row) < M;
            const float* gp = ok ? (X + (size_t)(m0 + row) * K + k0 + gg * 4) : X;
            uint32_t sa = (uint32_t)__cvta_generic_to_shared(asb + row * PA + gg * 4);
            int sz = ok ? 16 : 0;
            asm volatile("cp.async.cg.shared.global [%0], [%1], 16, %2;\n"
                         :: "r"(sa), "l"(gp), "r"(sz));
        }
#pragma unroll
        for (int i = 0; i < 2; i++) {
            int G = i * 256 + t;
            int kr = G >> 4, gn = G & 15;
            const float* gp = W + (size_t)(k0 + kr) * 64 + gn * 4;
            uint32_t sa = (uint32_t)__cvta_generic_to_shared(wsb + kr * PB + gn * 4);
            asm volatile("cp.async.cg.shared.global [%0], [%1], 16;\n"
                         :: "r"(sa), "l"(gp));
        }
    };

    load_stage(0, 0);
    asm volatile("cp.async.commit_group;\n");

    const int NIT = K / BK;
    for (int it = 0; it < NIT; it++) {
        if (it + 1 < NIT) load_stage((it + 1) & 1, (it + 1) * BK);
        asm volatile("cp.async.commit_group;\n");
        asm volatile("cp.async.wait_group 1;\n");
        __syncthreads();

        const float* asb = as + (it & 1) * BM * PA;
        const float* wsb = ws + (it & 1) * BK * PB;

#pragma unroll
        for (int ks = 0; ks < BK; ks += 8) {
            uint32_t a[2][4], b[4][2];
#pragma unroll
            for (int mt = 0; mt < 2; mt++) {
                int r = wm * 32 + mt * 16 + g;
                a[mt][0] = cvt_tf32(asb[r * PA + ks + tig]);
                a[mt][1] = cvt_tf32(asb[(r + 8) * PA + ks + tig]);
                a[mt][2] = cvt_tf32(asb[r * PA + ks + tig + 4]);
                a[mt][3] = cvt_tf32(asb[(r + 8) * PA + ks + tig + 4]);
            }
#pragma unroll
            for (int nt = 0; nt < 4; nt++) {
                int n = wn * 32 + nt * 8 + g;
                b[nt][0] = cvt_tf32(wsb[(ks + tig) * PB + n]);
                b[nt][1] = cvt_tf32(wsb[(ks + tig + 4) * PB + n]);
            }
#pragma unroll
            for (int mt = 0; mt < 2; mt++)
#pragma unroll
                for (int nt = 0; nt < 4; nt++) {
                    asm volatile(
                        "mma.sync.aligned.m16n8k8.row.col.f32.tf32.tf32.f32 "
                        "{%0,%1,%2,%3}, {%4,%5,%6,%7}, {%8,%9}, {%0,%1,%2,%3};"
                        : "+f"(c[mt][nt][0]), "+f"(c[mt][nt][1]),
                          "+f"(c[mt][nt][2]), "+f"(c[mt][nt][3])
                        : "r"(a[mt][0]), "r"(a[mt][1]), "r"(a[mt][2]), "r"(a[mt][3]),
                          "r"(b[nt][0]), "r"(b[nt][1]));
                }
        }
        __syncthreads();
    }

    // --- epilogue: hn[row] = acc * dinv[row]
#pragma unroll
    for (int mt = 0; mt < 2; mt++) {
        int rbase = m0 + wm * 32 + mt * 16 + g;
#pragma unroll
        for (int half = 0; half < 2; half++) {
            int row = rbase + half * 8;
            if (row < M) {
                float s = dinv[row];
#pragma unroll
                for (int nt = 0; nt < 4; nt++) {
                    float2 v;
                    v.x = c[mt][nt][half * 2 + 0] * s;
                    v.y = c[mt][nt][half * 2 + 1] * s;
                    *(float2*)(hn + (size_t)row * 64 + wn * 32 + nt * 8 + 2 * tig) = v;
                }
            }
        }
    }
}

// ---------------------------------------------------------------------------
// Fused aggregate: out[i] = act(dinv[i] * (hn[i] + sum_{e in CSR(i)} hn[col[e]]) + b)
// Warp per node, 2 columns per lane, 8 gathers in flight per chunk.
// ---------------------------------------------------------------------------
template <bool RELU>
__global__ void __launch_bounds__(256)
k_agg(const int* __restrict__ rowptr, const int* __restrict__ col,
      const float* __restrict__ hn, const float* __restrict__ dinv,
      const float* __restrict__ bias, float* __restrict__ out, int n) {
    int w = (blockIdx.x * blockDim.x + threadIdx.x) >> 5;
    int lane = threadIdx.x & 31;
    if (w >= n) return;

    const float* hrow = hn + (size_t)w * 64;
    float a0 = hrow[lane];         // self-loop term
    float a1 = hrow[lane + 32];

    int beg = __ldg(&rowptr[w]);
    int end = __ldg(&rowptr[w + 1]);

    for (int e0 = beg; e0 < end; e0 += 8) {
        int idx = e0 + (lane & 7);
        int cs = (idx < end) ? __ldg(&col[idx]) : -1;
#pragma unroll
        for (int j = 0; j < 8; j++) {
            int s = __shfl_sync(0xffffffffu, cs, j);
            if (s >= 0) {
                const float* hr = hn + (size_t)s * 64;
                a0 += __ldg(&hr[lane]);
                a1 += __ldg(&hr[lane + 32]);
            }
        }
    }

    float di = __ldg(&dinv[w]);
    float v0 = di * a0 + __ldg(&bias[lane]);
    float v1 = di * a1 + __ldg(&bias[lane + 32]);
    if (RELU) { v0 = fmaxf(v0, 0.0f); v1 = fmaxf(v1, 0.0f); }
    out[(size_t)w * 64 + lane]      = v0;
    out[(size_t)w * 64 + lane + 32] = v1;
}

// ---------------------------------------------------------------------------
// Launch
// ---------------------------------------------------------------------------
extern "C" void kernel_launch(void* const* d_in, const int* in_sizes, int n_in,
                              void* d_out, int out_size) {
    const float* x  = (const float*)d_in[0];
    const int*   ei = (const int*)d_in[1];
    const float* W1 = (const float*)d_in[2];
    const float* b1 = (const float*)d_in[3];
    const float* W2 = (const float*)d_in[4];
    const float* b2 = (const float*)d_in[5];

    const int E = in_sizes[1] / 2;
    const int M = out_size / HID;
    const int* src = ei;
    const int* dst = ei + E;

    float *dinv, *bufA, *bufB;
    int *cnt, *rowptr, *cursor, *col;
    cudaGetSymbolAddress((void**)&dinv,   g_dinv);
    cudaGetSymbolAddress((void**)&cnt,    g_cnt);
    cudaGetSymbolAddress((void**)&rowptr, g_rowptr);
    cudaGetSymbolAddress((void**)&cursor, g_cursor);
    cudaGetSymbolAddress((void**)&col,    g_col);
    cudaGetSymbolAddress((void**)&bufA,   g_bufA);
    cudaGetSymbolAddress((void**)&bufB,   g_bufB);
    float* out = (float*)d_out;

    static int smem_set = 0;
    if (!smem_set) {
        cudaFuncSetAttribute(k_gemm<IN_DIM>,
                             cudaFuncAttributeMaxDynamicSharedMemorySize, GEMM_SMEM_BYTES);
        cudaFuncSetAttribute(k_gemm<HID>,
                             cudaFuncAttributeMaxDynamicSharedMemorySize, GEMM_SMEM_BYTES);
        smem_set = 1;
    }

    // 1. CSR build + norms
    k_zero_cnt<<<(M + 255) / 256, 256>>>(cnt, M);
    k_count<<<(E + 255) / 256, 256>>>(dst, cnt, E);
    k_scan<<<1, 1024>>>(cnt, rowptr, cursor, dinv, M);
    k_fill<<<(E + 255) / 256, 256>>>(src, dst, cursor, col, E);

    const int gblk = (M + BM - 1) / BM;
    const int ablk = (M * 32 + 255) / 256;  // warp per node

    // 2. layer 1
    k_gemm<IN_DIM><<<gblk, 256, GEMM_SMEM_BYTES>>>(x, W1, dinv, bufA, M);
    k_agg<true><<<ablk, 256>>>(rowptr, col, bufA, dinv, b1, bufB, M);

    // 3. layer 2
    k_gemm<HID><<<gblk, 256, GEMM_SMEM_BYTES>>>(bufB, W2, dinv, bufA, M);
    k_agg<false><<<ablk, 256>>>(rowptr, col, bufA, dinv, b2, out, M);
}